// round 14
// baseline (speedup 1.0000x reference)
#include <cuda_runtime.h>

// Problem constants (fixed by setup_inputs)
#define DD   2048          // D
#define UU   37            // units
#define BB   16            // batch
#define CHUNK 8192         // floats per chunk of the D*D plane
#define NCHUNK ((DD*DD)/CHUNK)   // 512
#define NTHREADS 256
#define F4_PER_THREAD (CHUNK / 4 / NTHREADS)  // 8 float4 per thread

#define NDIAG  (UU * DD)                      // 75776 diagonal elems
#define GBLOCKS (NDIAG / NTHREADS)            // 296 (exact)
#define SLICES_PER_U (DD / NTHREADS)          // 8
#define NDVALS (BB + 1)                       // 17: [acc1, acc2[0..15]]

// Scratch (device globals; no allocation allowed)
__device__ float g_Spart[UU * NCHUNK];            // dense partials [u][chunk]
__device__ float g_diagpart[GBLOCKS * NDVALS];    // diag partials [slice][17]

// Kernel 1:
//  blocks [0, NCHUNK):        dense contraction partials — weight read once,
//                             relu(matrix) chunk cached in registers (MLP!).
//                             Per-u reduce DEFERRED: one STS per u, single
//                             block-wide reduce at the end (keeps the LDG
//                             burst duty-cycle high).
//  blocks [NCHUNK, +GBLOCKS): diagonal-term partial sums (cheap, overlapped).
__global__ void __launch_bounds__(NTHREADS) gfrm_partial_kernel(
    const float* __restrict__ inputs,
    const float* __restrict__ matrix,
    const float* __restrict__ weight)
{
    const int tid  = threadIdx.x;
    const int lane = tid & 31;
    const int wid  = tid >> 5;

    // PDL: allow the dependent finalize kernel to start dispatching early.
    if (tid == 0) cudaTriggerProgrammaticLaunchCompletion();

    if (blockIdx.x >= NCHUNK) {
        // ---- diagonal stage: one block per 256-element slice of one u ----
        const int slice = blockIdx.x - NCHUNK;        // 0..295
        const int g = slice * NTHREADS + tid;         // global diag index
        const int u = g >> 11;                        // constant per block
        const int i = g & (DD - 1);

        const float mii = matrix[(size_t)i * (DD + 1)];
        const float wii = __ldcs(weight + (size_t)u * DD * DD
                                        + (size_t)i * (DD + 1));

        float v[NDVALS];
        v[0] = fmaxf(mii, 0.0f) * wii;                // plain-diag term
#pragma unroll
        for (int b = 0; b < BB; b++) {
            const float x = inputs[b * DD + i];
            v[1 + b] = fmaxf(mii * x, 0.0f) * wii;    // batch-diag terms
        }

        // deterministic warp reduce of all 17 values
#pragma unroll
        for (int k = 0; k < NDVALS; k++) {
#pragma unroll
            for (int o = 16; o > 0; o >>= 1)
                v[k] += __shfl_xor_sync(0xffffffffu, v[k], o);
        }
        __shared__ float wpart[NDVALS][NTHREADS / 32];
        if (lane == 0) {
#pragma unroll
            for (int k = 0; k < NDVALS; k++) wpart[k][wid] = v[k];
        }
        __syncthreads();
        if (tid < NDVALS) {
            float s = 0.f;
#pragma unroll
            for (int w = 0; w < NTHREADS / 32; w++) s += wpart[tid][w];
            g_diagpart[slice * NDVALS + tid] = s;
        }
        return;
    }

    // ---- dense partial stage ----
    const int c = blockIdx.x;               // chunk id, 0..NCHUNK-1
    const size_t base = (size_t)c * CHUNK;  // float offset into D*D plane

    // Load + relu the matrix chunk into registers (coalesced float4).
    float4 m[F4_PER_THREAD];
    const float4* mp = reinterpret_cast<const float4*>(matrix + base);
#pragma unroll
    for (int k = 0; k < F4_PER_THREAD; k++) {
        float4 v = mp[k * NTHREADS + tid];
        m[k].x = fmaxf(v.x, 0.0f);
        m[k].y = fmaxf(v.y, 0.0f);
        m[k].z = fmaxf(v.z, 0.0f);
        m[k].w = fmaxf(v.w, 0.0f);
    }

    __shared__ float spart[UU][NTHREADS];   // per-thread partials, 37 KB

    for (int u = 0; u < UU; u++) {
        const float4* wp = reinterpret_cast<const float4*>(
            weight + (size_t)u * DD * DD + base);
        float s0 = 0.f, s1 = 0.f, s2 = 0.f, s3 = 0.f;
#pragma unroll
        for (int k = 0; k < F4_PER_THREAD; k++) {
            float4 w = __ldcs(wp + k * NTHREADS + tid);  // read-once stream
            s0 = fmaf(m[k].x, w.x, s0);
            s1 = fmaf(m[k].y, w.y, s1);
            s2 = fmaf(m[k].z, w.z, s2);
            s3 = fmaf(m[k].w, w.w, s3);
        }
        // defer the reduce: one conflict-free STS, no shuffle chain here
        spart[u][tid] = (s0 + s1) + (s2 + s3);
    }
    __syncthreads();

    // Single deferred reduce: warp w handles u = w, w+8, ...
    for (int u = wid; u < UU; u += NTHREADS / 32) {
        float v = 0.f;
#pragma unroll
        for (int j = 0; j < NTHREADS / 32; j++)
            v += spart[u][j * 32 + lane];
#pragma unroll
        for (int o = 16; o > 0; o >>= 1)
            v += __shfl_xor_sync(0xffffffffu, v, o);
        if (lane == 0) g_Spart[u * NCHUNK + c] = v;
    }
}

// Kernel 2 (PDL dependent): one warp per u, all L2-resident reads.
__global__ void __launch_bounds__(32) gfrm_final_kernel(
    const float* __restrict__ bias,
    float* __restrict__ out)
{
    const int u    = blockIdx.x;
    const int lane = threadIdx.x;

    // Wait until kernel1's writes are complete and visible.
    cudaGridDependencySynchronize();

    // Reduce 512 dense partials for this u (16 per lane, fixed order).
    float s = 0.f;
#pragma unroll
    for (int k = 0; k < NCHUNK / 32; k++)
        s += g_Spart[u * NCHUNK + k * 32 + lane];
#pragma unroll
    for (int o = 16; o > 0; o >>= 1)
        s += __shfl_xor_sync(0xffffffffu, s, o);   // all lanes hold S

    // Reduce the 8 diag slice-partials for this u (lanes 0..16).
    float d = 0.f;
    if (lane < NDVALS) {
#pragma unroll
        for (int sl = 0; sl < SLICES_PER_U; sl++)
            d += g_diagpart[(u * SLICES_PER_U + sl) * NDVALS + lane];
    }
    const float d0 = __shfl_sync(0xffffffffu, d, 0);

    if (lane >= 1 && lane <= BB) {
        out[(lane - 1) * UU + u] = s - d0 + d + bias[u];
    }
}

extern "C" void kernel_launch(void* const* d_in, const int* in_sizes, int n_in,
                              void* d_out, int out_size)
{
    const float* inputs = (const float*)d_in[0];  // (16, 2048)
    const float* matrix = (const float*)d_in[1];  // (2048, 2048)
    const float* weight = (const float*)d_in[2];  // (37, 2048, 2048)
    const float* bias   = (const float*)d_in[3];  // (37,)
    float* out = (float*)d_out;                    // (16, 37)

    gfrm_partial_kernel<<<NCHUNK + GBLOCKS, NTHREADS>>>(inputs, matrix, weight);

    // Dependent launch with programmatic stream serialization (PDL).
    cudaLaunchConfig_t cfg = {};
    cfg.gridDim  = dim3(UU);
    cfg.blockDim = dim3(32);
    cfg.dynamicSmemBytes = 0;
    cfg.stream = 0;
    cudaLaunchAttribute attr[1];
    attr[0].id = cudaLaunchAttributeProgrammaticStreamSerialization;
    attr[0].val.programmaticStreamSerializationAllowed = 1;
    cfg.attrs = attr;
    cfg.numAttrs = 1;
    cudaError_t e = cudaLaunchKernelEx(&cfg, gfrm_final_kernel,
                                       (const float*)bias, (float*)out);
    if (e != cudaSuccess) {
        // Fallback: plain stream-ordered launch (correctness identical).
        gfrm_final_kernel<<<UU, 32>>>(bias, out);
    }
}

// round 15
// speedup vs baseline: 1.2917x; 1.2917x over previous
#include <cuda_runtime.h>

// Problem constants (fixed by setup_inputs)
#define DD   2048          // D
#define UU   37            // units
#define BB   16            // batch
#define CHUNK 8192         // floats per chunk of the D*D plane
#define NCHUNK ((DD*DD)/CHUNK)   // 512
#define NTHREADS 256
#define F4_PER_THREAD (CHUNK / 4 / NTHREADS)  // 8 float4 per thread

#define NDIAG  (UU * DD)                      // 75776 diagonal elems
#define GBLOCKS (NDIAG / NTHREADS)            // 296 (exact)
#define SLICES_PER_U (DD / NTHREADS)          // 8
#define NDVALS (BB + 1)                       // 17: [acc1, acc2[0..15]]

// Scratch (device globals; no allocation allowed)
__device__ float g_Spart[UU * NCHUNK];            // dense partials [u][chunk]
__device__ float g_diagpart[GBLOCKS * NDVALS];    // diag partials [slice][17]

// Kernel 1 (R8 dense path — measured 6.89 TB/s; do not touch the loop body):
//  blocks [0, NCHUNK):        dense contraction partials — weight read once,
//                             relu(matrix) chunk cached in registers (MLP!),
//                             per-u warp-shuffle reduce (proven codegen).
//  blocks [NCHUNK, +GBLOCKS): diagonal-term partial sums (cheap, overlapped).
__global__ void __launch_bounds__(NTHREADS) gfrm_partial_kernel(
    const float* __restrict__ inputs,
    const float* __restrict__ matrix,
    const float* __restrict__ weight)
{
    const int tid  = threadIdx.x;
    const int lane = tid & 31;
    const int wid  = tid >> 5;

    // PDL: allow the dependent finalize kernel to start dispatching early.
    if (tid == 0) cudaTriggerProgrammaticLaunchCompletion();

    if (blockIdx.x >= NCHUNK) {
        // ---- diagonal stage: one block per 256-element slice of one u ----
        const int slice = blockIdx.x - NCHUNK;        // 0..295
        const int g = slice * NTHREADS + tid;         // global diag index
        const int u = g >> 11;                        // constant per block
        const int i = g & (DD - 1);

        const float mii = matrix[(size_t)i * (DD + 1)];
        const float wii = __ldcs(weight + (size_t)u * DD * DD
                                        + (size_t)i * (DD + 1));

        float v[NDVALS];
        v[0] = fmaxf(mii, 0.0f) * wii;                // plain-diag term
#pragma unroll
        for (int b = 0; b < BB; b++) {
            const float x = inputs[b * DD + i];
            v[1 + b] = fmaxf(mii * x, 0.0f) * wii;    // batch-diag terms
        }

        // deterministic warp reduce of all 17 values
#pragma unroll
        for (int k = 0; k < NDVALS; k++) {
#pragma unroll
            for (int o = 16; o > 0; o >>= 1)
                v[k] += __shfl_xor_sync(0xffffffffu, v[k], o);
        }
        __shared__ float wpart[NDVALS][NTHREADS / 32];
        if (lane == 0) {
#pragma unroll
            for (int k = 0; k < NDVALS; k++) wpart[k][wid] = v[k];
        }
        __syncthreads();
        if (tid < NDVALS) {
            float s = 0.f;
#pragma unroll
            for (int w = 0; w < NTHREADS / 32; w++) s += wpart[tid][w];
            g_diagpart[slice * NDVALS + tid] = s;
        }
        return;
    }

    // ---- dense partial stage ----
    const int c = blockIdx.x;               // chunk id, 0..NCHUNK-1
    const size_t base = (size_t)c * CHUNK;  // float offset into D*D plane

    // Load + relu the matrix chunk into registers (coalesced float4).
    float4 m[F4_PER_THREAD];
    const float4* mp = reinterpret_cast<const float4*>(matrix + base);
#pragma unroll
    for (int k = 0; k < F4_PER_THREAD; k++) {
        float4 v = mp[k * NTHREADS + tid];
        m[k].x = fmaxf(v.x, 0.0f);
        m[k].y = fmaxf(v.y, 0.0f);
        m[k].z = fmaxf(v.z, 0.0f);
        m[k].w = fmaxf(v.w, 0.0f);
    }

    __shared__ float warp_part[UU][NTHREADS / 32];

    for (int u = 0; u < UU; u++) {
        const float4* wp = reinterpret_cast<const float4*>(
            weight + (size_t)u * DD * DD + base);
        float s0 = 0.f, s1 = 0.f, s2 = 0.f, s3 = 0.f;
#pragma unroll
        for (int k = 0; k < F4_PER_THREAD; k++) {
            float4 w = __ldcs(wp + k * NTHREADS + tid);  // read-once stream
            s0 = fmaf(m[k].x, w.x, s0);
            s1 = fmaf(m[k].y, w.y, s1);
            s2 = fmaf(m[k].z, w.z, s2);
            s3 = fmaf(m[k].w, w.w, s3);
        }
        float s = (s0 + s1) + (s2 + s3);
        // deterministic warp reduce
#pragma unroll
        for (int o = 16; o > 0; o >>= 1)
            s += __shfl_xor_sync(0xffffffffu, s, o);
        if (lane == 0) warp_part[u][wid] = s;
    }
    __syncthreads();

    if (tid < UU) {
        float s = 0.f;
#pragma unroll
        for (int w = 0; w < NTHREADS / 32; w++) s += warp_part[tid][w];
        g_Spart[tid * NCHUNK + c] = s;
    }
}

// Kernel 2 (PDL dependent): one warp per u, all L2-resident reads.
__global__ void __launch_bounds__(32) gfrm_final_kernel(
    const float* __restrict__ bias,
    float* __restrict__ out)
{
    const int u    = blockIdx.x;
    const int lane = threadIdx.x;

    // Wait until kernel1's writes are complete and visible.
    cudaGridDependencySynchronize();

    // Reduce 512 dense partials for this u (16 per lane, fixed order).
    float s = 0.f;
#pragma unroll
    for (int k = 0; k < NCHUNK / 32; k++)
        s += g_Spart[u * NCHUNK + k * 32 + lane];
#pragma unroll
    for (int o = 16; o > 0; o >>= 1)
        s += __shfl_xor_sync(0xffffffffu, s, o);   // all lanes hold S

    // Reduce the 8 diag slice-partials for this u (lanes 0..16).
    float d = 0.f;
    if (lane < NDVALS) {
#pragma unroll
        for (int sl = 0; sl < SLICES_PER_U; sl++)
            d += g_diagpart[(u * SLICES_PER_U + sl) * NDVALS + lane];
    }
    const float d0 = __shfl_sync(0xffffffffu, d, 0);

    if (lane >= 1 && lane <= BB) {
        out[(lane - 1) * UU + u] = s - d0 + d + bias[u];
    }
}

extern "C" void kernel_launch(void* const* d_in, const int* in_sizes, int n_in,
                              void* d_out, int out_size)
{
    const float* inputs = (const float*)d_in[0];  // (16, 2048)
    const float* matrix = (const float*)d_in[1];  // (2048, 2048)
    const float* weight = (const float*)d_in[2];  // (37, 2048, 2048)
    const float* bias   = (const float*)d_in[3];  // (37,)
    float* out = (float*)d_out;                    // (16, 37)

    gfrm_partial_kernel<<<NCHUNK + GBLOCKS, NTHREADS>>>(inputs, matrix, weight);

    // Dependent launch with programmatic stream serialization (PDL).
    cudaLaunchConfig_t cfg = {};
    cfg.gridDim  = dim3(UU);
    cfg.blockDim = dim3(32);
    cfg.dynamicSmemBytes = 0;
    cfg.stream = 0;
    cudaLaunchAttribute attr[1];
    attr[0].id = cudaLaunchAttributeProgrammaticStreamSerialization;
    attr[0].val.programmaticStreamSerializationAllowed = 1;
    cfg.attrs = attr;
    cfg.numAttrs = 1;
    cudaError_t e = cudaLaunchKernelEx(&cfg, gfrm_final_kernel,
                                       (const float*)bias, (float*)out);
    if (e != cudaSuccess) {
        // Fallback: plain stream-ordered launch (correctness identical).
        gfrm_final_kernel<<<UU, 32>>>(bias, out);
    }
}

// round 16
// speedup vs baseline: 1.2946x; 1.0023x over previous
#include <cuda_runtime.h>

// Problem constants (fixed by setup_inputs)
#define DD   2048          // D
#define UU   37            // units
#define BB   16            // batch
#define CHUNK 8192         // floats per chunk of the D*D plane
#define NCHUNK ((DD*DD)/CHUNK)   // 512
#define NTHREADS 256
#define F4_PER_THREAD (CHUNK / 4 / NTHREADS)  // 8 float4 per thread

#define NDIAG  (UU * DD)                      // 75776 diagonal elems
#define GBLOCKS (NDIAG / NTHREADS)            // 296 (exact)
#define SLICES_PER_U (DD / NTHREADS)          // 8
#define NDVALS (BB + 1)                       // 17: [acc1, acc2[0..15]]

// Scratch (device globals; no allocation allowed)
__device__ float g_Spart[UU * NCHUNK];            // dense partials [u][chunk]
__device__ float g_diagpart[GBLOCKS * NDVALS];    // diag partials [slice][17]

// Kernel 1 (R8 dense path — measured 6.89 TB/s; loop body is load-bearing,
// do not restructure: both the smem-m variant (R5) and the deferred-reduce
// variant (R10) regressed it badly):
//  blocks [0, NCHUNK):        dense contraction partials — weight read once,
//                             relu(matrix) chunk cached in registers (MLP!),
//                             per-u warp-shuffle reduce (proven codegen).
//  blocks [NCHUNK, +GBLOCKS): diagonal-term partial sums (cheap, overlapped).
__global__ void __launch_bounds__(NTHREADS) gfrm_partial_kernel(
    const float* __restrict__ inputs,
    const float* __restrict__ matrix,
    const float* __restrict__ weight)
{
    const int tid  = threadIdx.x;
    const int lane = tid & 31;
    const int wid  = tid >> 5;

    // PDL: allow the dependent finalize kernel to start dispatching early.
    if (tid == 0) cudaTriggerProgrammaticLaunchCompletion();

    if (blockIdx.x >= NCHUNK) {
        // ---- diagonal stage: one block per 256-element slice of one u ----
        const int slice = blockIdx.x - NCHUNK;        // 0..295
        const int g = slice * NTHREADS + tid;         // global diag index
        const int u = g >> 11;                        // constant per block
        const int i = g & (DD - 1);

        const float mii = matrix[(size_t)i * (DD + 1)];
        const float wii = __ldcs(weight + (size_t)u * DD * DD
                                        + (size_t)i * (DD + 1));

        float v[NDVALS];
        v[0] = fmaxf(mii, 0.0f) * wii;                // plain-diag term
#pragma unroll
        for (int b = 0; b < BB; b++) {
            const float x = inputs[b * DD + i];
            v[1 + b] = fmaxf(mii * x, 0.0f) * wii;    // batch-diag terms
        }

        // deterministic warp reduce of all 17 values
#pragma unroll
        for (int k = 0; k < NDVALS; k++) {
#pragma unroll
            for (int o = 16; o > 0; o >>= 1)
                v[k] += __shfl_xor_sync(0xffffffffu, v[k], o);
        }
        __shared__ float wpart[NDVALS][NTHREADS / 32];
        if (lane == 0) {
#pragma unroll
            for (int k = 0; k < NDVALS; k++) wpart[k][wid] = v[k];
        }
        __syncthreads();
        if (tid < NDVALS) {
            float s = 0.f;
#pragma unroll
            for (int w = 0; w < NTHREADS / 32; w++) s += wpart[tid][w];
            g_diagpart[slice * NDVALS + tid] = s;
        }
        return;
    }

    // ---- dense partial stage ----
    const int c = blockIdx.x;               // chunk id, 0..NCHUNK-1
    const size_t base = (size_t)c * CHUNK;  // float offset into D*D plane

    // Load + relu the matrix chunk into registers (coalesced float4).
    float4 m[F4_PER_THREAD];
    const float4* mp = reinterpret_cast<const float4*>(matrix + base);
#pragma unroll
    for (int k = 0; k < F4_PER_THREAD; k++) {
        float4 v = mp[k * NTHREADS + tid];
        m[k].x = fmaxf(v.x, 0.0f);
        m[k].y = fmaxf(v.y, 0.0f);
        m[k].z = fmaxf(v.z, 0.0f);
        m[k].w = fmaxf(v.w, 0.0f);
    }

    __shared__ float warp_part[UU][NTHREADS / 32];

    for (int u = 0; u < UU; u++) {
        const float4* wp = reinterpret_cast<const float4*>(
            weight + (size_t)u * DD * DD + base);
        float s0 = 0.f, s1 = 0.f, s2 = 0.f, s3 = 0.f;
#pragma unroll
        for (int k = 0; k < F4_PER_THREAD; k++) {
            float4 w = __ldcs(wp + k * NTHREADS + tid);  // read-once stream
            s0 = fmaf(m[k].x, w.x, s0);
            s1 = fmaf(m[k].y, w.y, s1);
            s2 = fmaf(m[k].z, w.z, s2);
            s3 = fmaf(m[k].w, w.w, s3);
        }
        float s = (s0 + s1) + (s2 + s3);
        // deterministic warp reduce
#pragma unroll
        for (int o = 16; o > 0; o >>= 1)
            s += __shfl_xor_sync(0xffffffffu, s, o);
        if (lane == 0) warp_part[u][wid] = s;
    }
    __syncthreads();

    if (tid < UU) {
        float s = 0.f;
#pragma unroll
        for (int w = 0; w < NTHREADS / 32; w++) s += warp_part[tid][w];
        g_Spart[tid * NCHUNK + c] = s;
    }
}

// Kernel 2 (PDL dependent, R8 shape: 256 threads per u — widest parallel
// pull of the partials immediately after the dependency releases).
__global__ void __launch_bounds__(NTHREADS) gfrm_final_kernel(
    const float* __restrict__ bias,
    float* __restrict__ out)
{
    const int u    = blockIdx.x;
    const int tid  = threadIdx.x;
    const int lane = tid & 31;
    const int wid  = tid >> 5;

    // Wait until kernel1's writes are complete and visible.
    cudaGridDependencySynchronize();

    // Reduce 512 dense partials for this u (2 per thread, then tree).
    float s = g_Spart[u * NCHUNK + tid] + g_Spart[u * NCHUNK + NTHREADS + tid];
#pragma unroll
    for (int o = 16; o > 0; o >>= 1)
        s += __shfl_xor_sync(0xffffffffu, s, o);

    __shared__ float ws[NTHREADS / 32];
    __shared__ float diag[NDVALS];
    if (lane == 0) ws[wid] = s;

    // Reduce the 8 diag slice-partials for this u.
    if (tid < NDVALS) {
        float d = 0.f;
#pragma unroll
        for (int sl = 0; sl < SLICES_PER_U; sl++)
            d += g_diagpart[(u * SLICES_PER_U + sl) * NDVALS + tid];
        diag[tid] = d;
    }
    __syncthreads();

    if (tid < BB) {
        float S = 0.f;
#pragma unroll
        for (int w = 0; w < NTHREADS / 32; w++) S += ws[w];
        out[tid * UU + u] = S - diag[0] + diag[1 + tid] + bias[u];
    }
}

extern "C" void kernel_launch(void* const* d_in, const int* in_sizes, int n_in,
                              void* d_out, int out_size)
{
    const float* inputs = (const float*)d_in[0];  // (16, 2048)
    const float* matrix = (const float*)d_in[1];  // (2048, 2048)
    const float* weight = (const float*)d_in[2];  // (37, 2048, 2048)
    const float* bias   = (const float*)d_in[3];  // (37,)
    float* out = (float*)d_out;                    // (16, 37)

    gfrm_partial_kernel<<<NCHUNK + GBLOCKS, NTHREADS>>>(inputs, matrix, weight);

    // Dependent launch with programmatic stream serialization (PDL).
    cudaLaunchConfig_t cfg = {};
    cfg.gridDim  = dim3(UU);
    cfg.blockDim = dim3(NTHREADS);
    cfg.dynamicSmemBytes = 0;
    cfg.stream = 0;
    cudaLaunchAttribute attr[1];
    attr[0].id = cudaLaunchAttributeProgrammaticStreamSerialization;
    attr[0].val.programmaticStreamSerializationAllowed = 1;
    cfg.attrs = attr;
    cfg.numAttrs = 1;
    cudaError_t e = cudaLaunchKernelEx(&cfg, gfrm_final_kernel,
                                       (const float*)bias, (float*)out);
    if (e != cudaSuccess) {
        // Fallback: plain stream-ordered launch (correctness identical).
        gfrm_final_kernel<<<UU, NTHREADS>>>(bias, out);
    }
}